// round 6
// baseline (speedup 1.0000x reference)
#include <cuda_runtime.h>

#define NROWS 45000
#define NNZ   1485000     // 45000 * 33
#define BATCH 32
#define TSTEPS 100
#define NB    444         // k_step blocks = 3 per SM exactly; ~3345 entries each
#define ENT_CAP 4608      // 3345 avg + max boundary row degree (~600) + slack
#define BIGT  224         // rows with degree >= BIGT processed block-cooperatively

// tile-major permutation: 150x300 sheet in 10x10 tiles (15x30 tile grid)
__host__ __device__ __forceinline__ int perm_of(int r) {
    int i = r / 300, j = r % 300;
    return ((i / 10) * 30 + (j / 10)) * 100 + (i % 10) * 10 + (j % 10);
}

// ---------------- persistent device scratch (no allocations allowed) ----------------
__device__ float g_h[2][NROWS * BATCH];   // ping-pong hidden state, (N, B) row-major, ORIGINAL ids
__device__ int2  g_csr[NNZ];              // packed {col, val-as-int}, grouped by PERM row id
__device__ int   g_rowptr[NROWS + 1];     // over perm ids
__device__ int   g_wp[NROWS + 1];
__device__ int   g_cnt[NROWS];
__device__ int   g_rowof[NROWS];          // perm id -> original row id
__device__ int   g_bstart[NB + 1];        // entry-balanced block ranges (perm ids)
__device__ float g_t1[BATCH * 64];        // fc1 accumulator

// ---------------- CSR build ----------------
__global__ void k_zero() {
    int i = blockIdx.x * blockDim.x + threadIdx.x;
    if (i < NROWS) {
        g_cnt[i] = 0;
        g_rowof[perm_of(i)] = i;
    }
    if (i < BATCH * 64) g_t1[i] = 0.f;
}

__global__ void k_hist(const int* __restrict__ rows) {
    int i = blockIdx.x * blockDim.x + threadIdx.x;
    if (i < NNZ) atomicAdd(&g_cnt[perm_of(rows[i])], 1);
}

// single-block exclusive scan over 45000 counts + entry-balanced block partition
__global__ void k_scan() {
    __shared__ int ssum[1024];
    int t = threadIdx.x;
    const int CH = (NROWS + 1023) / 1024;   // 44
    int begin = t * CH;
    int end   = begin + CH; if (end > NROWS) end = NROWS;
    int s = 0;
    for (int i = begin; i < end; i++) s += g_cnt[i];
    ssum[t] = s;
    __syncthreads();
    for (int off = 1; off < 1024; off <<= 1) {
        int v = 0;
        if (t >= off) v = ssum[t - off];
        __syncthreads();
        if (t >= off) ssum[t] += v;
        __syncthreads();
    }
    int run = (t == 0) ? 0 : ssum[t - 1];
    for (int i = begin; i < end; i++) {
        g_rowptr[i] = run;
        g_wp[i]     = run;
        run += g_cnt[i];
    }
    if (t == 1023) { g_rowptr[NROWS] = ssum[1023]; g_wp[NROWS] = ssum[1023]; }
    __syncthreads();
    // entry-balanced partition: g_bstart[b] = lower_bound(rowptr, b*NNZ/NB)
    if (t <= NB) {
        long long target = ((long long)NNZ * t) / NB;
        int lo = 0, hi = NROWS;
        while (lo < hi) {
            int mid = (lo + hi) >> 1;
            if ((long long)g_rowptr[mid] < target) lo = mid + 1; else hi = mid;
        }
        g_bstart[t] = lo;
    }
}

__global__ void k_scatter(const int* __restrict__ rows, const int* __restrict__ cols,
                          const float* __restrict__ vals) {
    int i = blockIdx.x * blockDim.x + threadIdx.x;
    if (i < NNZ) {
        int pr = perm_of(rows[i]);
        int p = atomicAdd(&g_wp[pr], 1);
        g_csr[p] = make_int2(cols[i], __float_as_int(vals[i]));
    }
}

// ---------------- h init: h[n][b] = x[b][n] ----------------
__global__ void k_init_h(const float* __restrict__ x) {
    int idx = blockIdx.x * blockDim.x + threadIdx.x;
    if (idx < NROWS * BATCH) {
        int n = idx >> 5, b = idx & 31;
        g_h[0][idx] = x[b * NROWS + n];
    }
}

// ---------------- one RNN step ----------------
// smem-staged CSR (perm-grouped); entry-balanced warp<-row ranges; mega-rows
// block-cooperative; lane = (entry-group, batch-quad). Gathers hit L1 thanks
// to 2D tile locality of the perm ordering.
__global__ void __launch_bounds__(512) k_step(const float* __restrict__ bias, int par) {
    __shared__ int2   se[ENT_CAP];
    __shared__ float4 sred[16][8];
    __shared__ int    slist[64];
    __shared__ int    snbig;

    int b = blockIdx.x;
    int r0 = g_bstart[b], r1 = g_bstart[b + 1];
    int e0 = g_rowptr[r0];
    int ne = g_rowptr[r1] - e0;

    if (threadIdx.x == 0) snbig = 0;

    for (int i = threadIdx.x; i < ne; i += 512)
        se[i] = g_csr[e0 + i];
    __syncthreads();

    // collect mega-rows (perm ids)
    for (int r = r0 + threadIdx.x; r < r1; r += 512) {
        if (g_rowptr[r + 1] - g_rowptr[r] >= BIGT) {
            int i = atomicAdd(&snbig, 1);
            slist[i] = r;
        }
    }
    __syncthreads();

    const float* __restrict__ hin = g_h[par];
    float* __restrict__ hout = g_h[par ^ 1];
    int lane = threadIdx.x & 31;
    int warp = threadIdx.x >> 5;
    int grp  = lane >> 3;          // which of 4 entries in a group
    int bq   = (lane & 7) << 2;    // batch-quad offset: 0,4,...,28

    // per-warp entry-balanced row range [rs, re)
    int rs, re;
    {
        long long tg0 = e0 + ((long long)ne * warp) / 16;
        long long tg1 = e0 + ((long long)ne * (warp + 1)) / 16;
        int lo = r0, hi = r1;
        while (lo < hi) { int m = (lo + hi) >> 1; if ((long long)g_rowptr[m] < tg0) lo = m + 1; else hi = m; }
        rs = lo;
        lo = rs; hi = r1;
        while (lo < hi) { int m = (lo + hi) >> 1; if ((long long)g_rowptr[m] < tg1) lo = m + 1; else hi = m; }
        re = lo;
    }

    int s = (rs < re) ? (g_rowptr[rs] - e0) : 0;
    for (int r = rs; r < re; r++) {
        int e = g_rowptr[r + 1] - e0;
        if (e - s >= BIGT) { s = e; continue; }   // mega-row handled below
        float ax = 0.f, ay = 0.f, az = 0.f, aw = 0.f;

        for (int p = s; p < e; p += 8) {
            int  ei0 = p + grp;
            int  ei1 = p + 4 + grp;
            bool ok0 = ei0 < e;
            bool ok1 = ei1 < e;
            int2 q0 = se[ok0 ? ei0 : s];
            int2 q1 = se[ok1 ? ei1 : s];
            float v0 = ok0 ? __int_as_float(q0.y) : 0.f;
            float v1 = ok1 ? __int_as_float(q1.y) : 0.f;
            float4 h0 = *reinterpret_cast<const float4*>(hin + (q0.x << 5) + bq);
            float4 h1 = *reinterpret_cast<const float4*>(hin + (q1.x << 5) + bq);
            ax = fmaf(v0, h0.x, ax);  ay = fmaf(v0, h0.y, ay);
            az = fmaf(v0, h0.z, az);  aw = fmaf(v0, h0.w, aw);
            ax = fmaf(v1, h1.x, ax);  ay = fmaf(v1, h1.y, ay);
            az = fmaf(v1, h1.z, az);  aw = fmaf(v1, h1.w, aw);
        }

        ax += __shfl_xor_sync(0xffffffffu, ax, 8);
        ay += __shfl_xor_sync(0xffffffffu, ay, 8);
        az += __shfl_xor_sync(0xffffffffu, az, 8);
        aw += __shfl_xor_sync(0xffffffffu, aw, 8);
        ax += __shfl_xor_sync(0xffffffffu, ax, 16);
        ay += __shfl_xor_sync(0xffffffffu, ay, 16);
        az += __shfl_xor_sync(0xffffffffu, az, 16);
        aw += __shfl_xor_sync(0xffffffffu, aw, 16);

        if (lane < 8) {
            int ro = g_rowof[r];
            float bs = __ldg(bias + ro);
            float4 o;
            o.x = fmaxf(ax + bs, 0.f);
            o.y = fmaxf(ay + bs, 0.f);
            o.z = fmaxf(az + bs, 0.f);
            o.w = fmaxf(aw + bs, 0.f);
            *reinterpret_cast<float4*>(hout + (ro << 5) + bq) = o;
        }
        s = e;
    }

    // block-cooperative mega-rows: 128 entries/iter across 16 warps
    int nbig = snbig;
    for (int ib = 0; ib < nbig; ib++) {
        int r  = slist[ib];
        int ss = g_rowptr[r] - e0;
        int ee = g_rowptr[r + 1] - e0;
        float ax = 0.f, ay = 0.f, az = 0.f, aw = 0.f;

        for (int p = ss + warp * 8; p < ee; p += 128) {
            int  ei0 = p + grp;
            int  ei1 = p + 4 + grp;
            bool ok0 = ei0 < ee;
            bool ok1 = ei1 < ee;
            int2 q0 = se[ok0 ? ei0 : ss];
            int2 q1 = se[ok1 ? ei1 : ss];
            float v0 = ok0 ? __int_as_float(q0.y) : 0.f;
            float v1 = ok1 ? __int_as_float(q1.y) : 0.f;
            float4 h0 = *reinterpret_cast<const float4*>(hin + (q0.x << 5) + bq);
            float4 h1 = *reinterpret_cast<const float4*>(hin + (q1.x << 5) + bq);
            ax = fmaf(v0, h0.x, ax);  ay = fmaf(v0, h0.y, ay);
            az = fmaf(v0, h0.z, az);  aw = fmaf(v0, h0.w, aw);
            ax = fmaf(v1, h1.x, ax);  ay = fmaf(v1, h1.y, ay);
            az = fmaf(v1, h1.z, az);  aw = fmaf(v1, h1.w, aw);
        }

        ax += __shfl_xor_sync(0xffffffffu, ax, 8);
        ay += __shfl_xor_sync(0xffffffffu, ay, 8);
        az += __shfl_xor_sync(0xffffffffu, az, 8);
        aw += __shfl_xor_sync(0xffffffffu, aw, 8);
        ax += __shfl_xor_sync(0xffffffffu, ax, 16);
        ay += __shfl_xor_sync(0xffffffffu, ay, 16);
        az += __shfl_xor_sync(0xffffffffu, az, 16);
        aw += __shfl_xor_sync(0xffffffffu, aw, 16);

        if (lane < 8) sred[warp][lane] = make_float4(ax, ay, az, aw);
        __syncthreads();
        if (threadIdx.x < 8) {
            float4 acc = sred[0][threadIdx.x];
#pragma unroll
            for (int k = 1; k < 16; k++) {
                float4 t = sred[k][threadIdx.x];
                acc.x += t.x; acc.y += t.y; acc.z += t.z; acc.w += t.w;
            }
            int ro = g_rowof[r];
            float bs = __ldg(bias + ro);
            float4 o;
            o.x = fmaxf(acc.x + bs, 0.f);
            o.y = fmaxf(acc.y + bs, 0.f);
            o.z = fmaxf(acc.z + bs, 0.f);
            o.w = fmaxf(acc.w + bs, 0.f);
            *reinterpret_cast<float4*>(hout + (ro << 5) + (threadIdx.x << 2)) = o;
        }
        __syncthreads();
    }
}

// ---------------- fc1 partial: t1[b][m] += sum_n h[n][b] * w1[n][m] ----------------
__global__ void __launch_bounds__(256) k_fc1(const float* __restrict__ w1) {
    int t = threadIdx.x;
    int b  = t >> 3;            // 0..31
    int mg = (t & 7) << 3;      // m base: 0,8,...,56
    float acc[8];
#pragma unroll
    for (int j = 0; j < 8; j++) acc[j] = 0.f;

    int per = (NROWS + gridDim.x - 1) / gridDim.x;
    int n0 = blockIdx.x * per;
    int n1 = n0 + per; if (n1 > NROWS) n1 = NROWS;

    for (int n = n0; n < n1; n++) {
        float hv = g_h[0][(n << 5) | b];   // after 100 steps result is in parity 0
        const float4* w4 = reinterpret_cast<const float4*>(w1 + n * 64 + mg);
        float4 wa = __ldg(&w4[0]);
        float4 wb = __ldg(&w4[1]);
        acc[0] = fmaf(hv, wa.x, acc[0]);
        acc[1] = fmaf(hv, wa.y, acc[1]);
        acc[2] = fmaf(hv, wa.z, acc[2]);
        acc[3] = fmaf(hv, wa.w, acc[3]);
        acc[4] = fmaf(hv, wb.x, acc[4]);
        acc[5] = fmaf(hv, wb.y, acc[5]);
        acc[6] = fmaf(hv, wb.z, acc[6]);
        acc[7] = fmaf(hv, wb.w, acc[7]);
    }
#pragma unroll
    for (int j = 0; j < 8; j++) atomicAdd(&g_t1[b * 64 + mg + j], acc[j]);
}

// ---------------- fc2 ----------------
__global__ void k_fc2(const float* __restrict__ b1, const float* __restrict__ w2,
                      const float* __restrict__ b2, float* __restrict__ out) {
    int t = threadIdx.x;
    if (t >= BATCH * 10) return;
    int b = t / 10, j = t % 10;
    float acc = b2[j];
#pragma unroll 8
    for (int m = 0; m < 64; m++) {
        float u = fmaxf(g_t1[b * 64 + m] + b1[m], 0.f);
        acc = fmaf(u, w2[m * 10 + j], acc);
    }
    out[b * 10 + j] = acc;
}

// ---------------- launch ----------------
extern "C" void kernel_launch(void* const* d_in, const int* in_sizes, int n_in,
                              void* d_out, int out_size) {
    const float* x    = (const float*)d_in[0];
    const float* vals = (const float*)d_in[1];
    const float* bias = (const float*)d_in[2];
    const float* w1   = (const float*)d_in[3];
    const float* b1   = (const float*)d_in[4];
    const float* w2   = (const float*)d_in[5];
    const float* b2   = (const float*)d_in[6];
    const int*   rows = (const int*)d_in[7];
    const int*   cols = (const int*)d_in[8];
    (void)in_sizes; (void)n_in; (void)out_size;

    k_zero   <<<(NROWS + 255) / 256, 256>>>();
    k_hist   <<<(NNZ + 255) / 256, 256>>>(rows);
    k_scan   <<<1, 1024>>>();
    k_scatter<<<(NNZ + 255) / 256, 256>>>(rows, cols, vals);

    k_init_h <<<(NROWS * BATCH + 255) / 256, 256>>>(x);

    for (int t = 0; t < TSTEPS; t++)
        k_step<<<NB, 512>>>(bias, t & 1);

    k_fc1<<<128, 256>>>(w1);
    k_fc2<<<1, 320>>>(b1, w2, b2, (float*)d_out);
}

// round 7
// speedup vs baseline: 1.1097x; 1.1097x over previous
#include <cuda_runtime.h>

#define NROWS 45000
#define NNZ   1485000     // 45000 * 33
#define BATCH 32
#define TSTEPS 100
#define NB    444         // 3 blocks per SM exactly; ~3345 entries each
#define ENT_CAP 4608      // 3345 avg + max boundary row degree (~600) + slack
#define ROW_CAP 640       // max rows per block (avg ~101; min degree >= 6 so < 640)
#define BIGT  224         // rows with degree >= BIGT processed block-cooperatively

// ---------------- persistent device scratch (no allocations allowed) ----------------
__device__ float g_h[2][NROWS * BATCH];   // ping-pong hidden state, (N, B) row-major
__device__ int2  g_csr[NNZ];              // packed {col, val-as-int} per CSR entry
__device__ int   g_rowptr[NROWS + 1];
__device__ int   g_wp[NROWS + 1];
__device__ int   g_cnt[NROWS];
__device__ int   g_bstart[NB + 1];        // entry-balanced block row ranges
__device__ float g_t1[BATCH * 64];        // fc1 accumulator
__device__ volatile int g_gen;            // grid-barrier generation
__device__ int   g_arrive;                // grid-barrier arrival counter

// ---------------- CSR build ----------------
__global__ void k_zero() {
    int i = blockIdx.x * blockDim.x + threadIdx.x;
    if (i < NROWS) g_cnt[i] = 0;
    if (i < BATCH * 64) g_t1[i] = 0.f;
}

__global__ void k_hist(const int* __restrict__ rows) {
    int i = blockIdx.x * blockDim.x + threadIdx.x;
    if (i < NNZ) atomicAdd(&g_cnt[rows[i]], 1);
}

// single-block exclusive scan over 45000 counts + entry-balanced block partition
__global__ void k_scan() {
    __shared__ int ssum[1024];
    int t = threadIdx.x;
    const int CH = (NROWS + 1023) / 1024;   // 44
    int begin = t * CH;
    int end   = begin + CH; if (end > NROWS) end = NROWS;
    int s = 0;
    for (int i = begin; i < end; i++) s += g_cnt[i];
    ssum[t] = s;
    __syncthreads();
    for (int off = 1; off < 1024; off <<= 1) {
        int v = 0;
        if (t >= off) v = ssum[t - off];
        __syncthreads();
        if (t >= off) ssum[t] += v;
        __syncthreads();
    }
    int run = (t == 0) ? 0 : ssum[t - 1];
    for (int i = begin; i < end; i++) {
        g_rowptr[i] = run;
        g_wp[i]     = run;
        run += g_cnt[i];
    }
    if (t == 1023) { g_rowptr[NROWS] = ssum[1023]; g_wp[NROWS] = ssum[1023]; }
    __syncthreads();
    if (t <= NB) {
        long long target = ((long long)NNZ * t) / NB;
        int lo = 0, hi = NROWS;
        while (lo < hi) {
            int mid = (lo + hi) >> 1;
            if ((long long)g_rowptr[mid] < target) lo = mid + 1; else hi = mid;
        }
        g_bstart[t] = lo;
    }
}

__global__ void k_scatter(const int* __restrict__ rows, const int* __restrict__ cols,
                          const float* __restrict__ vals) {
    int i = blockIdx.x * blockDim.x + threadIdx.x;
    if (i < NNZ) {
        int r = rows[i];
        int p = atomicAdd(&g_wp[r], 1);
        g_csr[p] = make_int2(cols[i], __float_as_int(vals[i]));
    }
}

// ---------------- h init: h[n][b] = x[b][n] ----------------
__global__ void k_init_h(const float* __restrict__ x) {
    int idx = blockIdx.x * blockDim.x + threadIdx.x;
    if (idx < NROWS * BATCH) {
        int n = idx >> 5, b = idx & 31;
        g_h[0][idx] = x[b * NROWS + n];
    }
}

// ---------------- persistent RNN: all 100 steps in one kernel ----------------
// CSR + rowptr + bias staged to smem ONCE; entry-balanced warp<-row ranges;
// mega-rows block-cooperative; custom grid barrier between steps.
__global__ void __launch_bounds__(512, 3) k_run(const float* __restrict__ bias) {
    __shared__ int2   se[ENT_CAP];
    __shared__ float4 sred[16][8];
    __shared__ int    slist[64];
    __shared__ int    snbig;
    __shared__ int    srow[ROW_CAP + 1];   // rowptr deltas (local)
    __shared__ float  sbias[ROW_CAP];

    int b = blockIdx.x;
    int r0 = g_bstart[b], r1 = g_bstart[b + 1];
    int e0 = g_rowptr[r0];
    int ne = g_rowptr[r1] - e0;
    int nrows = r1 - r0;

    if (threadIdx.x == 0) snbig = 0;

    for (int i = threadIdx.x; i < ne; i += 512)
        se[i] = g_csr[e0 + i];
    for (int i = threadIdx.x; i <= nrows; i += 512) {
        srow[i] = g_rowptr[r0 + i] - e0;
        if (i < nrows) sbias[i] = bias[r0 + i];
    }
    __syncthreads();

    // collect mega-rows (local indices)
    for (int rl = threadIdx.x; rl < nrows; rl += 512) {
        if (srow[rl + 1] - srow[rl] >= BIGT) {
            int i = atomicAdd(&snbig, 1);
            slist[i] = rl;
        }
    }
    __syncthreads();

    int lane = threadIdx.x & 31;
    int warp = threadIdx.x >> 5;
    int grp  = lane >> 3;          // which of 4 entries in a group
    int bq   = (lane & 7) << 2;    // batch-quad offset: 0,4,...,28

    // per-warp entry-balanced row range [rsl, rel) (local), precomputed once
    int rsl, rel;
    {
        int tg0 = (int)(((long long)ne * warp) / 16);
        int tg1 = (int)(((long long)ne * (warp + 1)) / 16);
        int lo = 0, hi = nrows;
        while (lo < hi) { int m = (lo + hi) >> 1; if (srow[m] < tg0) lo = m + 1; else hi = m; }
        rsl = lo;
        lo = rsl; hi = nrows;
        while (lo < hi) { int m = (lo + hi) >> 1; if (srow[m] < tg1) lo = m + 1; else hi = m; }
        rel = lo;
    }
    int s_init = (rsl < rel) ? srow[rsl] : 0;
    int nbig = snbig;

    for (int t = 0; t < TSTEPS; t++) {
        int par = t & 1;
        const float* __restrict__ hin = g_h[par];
        float* __restrict__ hout = g_h[par ^ 1];

        int s = s_init;
        for (int rl = rsl; rl < rel; rl++) {
            int e = srow[rl + 1];
            if (e - s >= BIGT) { s = e; continue; }   // mega-row handled below
            float ax = 0.f, ay = 0.f, az = 0.f, aw = 0.f;

            for (int p = s; p < e; p += 8) {
                int  ei0 = p + grp;
                int  ei1 = p + 4 + grp;
                bool ok0 = ei0 < e;
                bool ok1 = ei1 < e;
                int2 q0 = se[ok0 ? ei0 : s];
                int2 q1 = se[ok1 ? ei1 : s];
                float v0 = ok0 ? __int_as_float(q0.y) : 0.f;
                float v1 = ok1 ? __int_as_float(q1.y) : 0.f;
                float4 h0 = *reinterpret_cast<const float4*>(hin + (q0.x << 5) + bq);
                float4 h1 = *reinterpret_cast<const float4*>(hin + (q1.x << 5) + bq);
                ax = fmaf(v0, h0.x, ax);  ay = fmaf(v0, h0.y, ay);
                az = fmaf(v0, h0.z, az);  aw = fmaf(v0, h0.w, aw);
                ax = fmaf(v1, h1.x, ax);  ay = fmaf(v1, h1.y, ay);
                az = fmaf(v1, h1.z, az);  aw = fmaf(v1, h1.w, aw);
            }

            ax += __shfl_xor_sync(0xffffffffu, ax, 8);
            ay += __shfl_xor_sync(0xffffffffu, ay, 8);
            az += __shfl_xor_sync(0xffffffffu, az, 8);
            aw += __shfl_xor_sync(0xffffffffu, aw, 8);
            ax += __shfl_xor_sync(0xffffffffu, ax, 16);
            ay += __shfl_xor_sync(0xffffffffu, ay, 16);
            az += __shfl_xor_sync(0xffffffffu, az, 16);
            aw += __shfl_xor_sync(0xffffffffu, aw, 16);

            if (lane < 8) {
                float bs = sbias[rl];
                float4 o;
                o.x = fmaxf(ax + bs, 0.f);
                o.y = fmaxf(ay + bs, 0.f);
                o.z = fmaxf(az + bs, 0.f);
                o.w = fmaxf(aw + bs, 0.f);
                *reinterpret_cast<float4*>(hout + ((r0 + rl) << 5) + bq) = o;
            }
            s = e;
        }

        // block-cooperative mega-rows: 128 entries/iter across 16 warps
        for (int ib = 0; ib < nbig; ib++) {
            int rl = slist[ib];
            int ss = srow[rl];
            int ee = srow[rl + 1];
            float ax = 0.f, ay = 0.f, az = 0.f, aw = 0.f;

            for (int p = ss + warp * 8; p < ee; p += 128) {
                int  ei0 = p + grp;
                int  ei1 = p + 4 + grp;
                bool ok0 = ei0 < ee;
                bool ok1 = ei1 < ee;
                int2 q0 = se[ok0 ? ei0 : ss];
                int2 q1 = se[ok1 ? ei1 : ss];
                float v0 = ok0 ? __int_as_float(q0.y) : 0.f;
                float v1 = ok1 ? __int_as_float(q1.y) : 0.f;
                float4 h0 = *reinterpret_cast<const float4*>(hin + (q0.x << 5) + bq);
                float4 h1 = *reinterpret_cast<const float4*>(hin + (q1.x << 5) + bq);
                ax = fmaf(v0, h0.x, ax);  ay = fmaf(v0, h0.y, ay);
                az = fmaf(v0, h0.z, az);  aw = fmaf(v0, h0.w, aw);
                ax = fmaf(v1, h1.x, ax);  ay = fmaf(v1, h1.y, ay);
                az = fmaf(v1, h1.z, az);  aw = fmaf(v1, h1.w, aw);
            }

            ax += __shfl_xor_sync(0xffffffffu, ax, 8);
            ay += __shfl_xor_sync(0xffffffffu, ay, 8);
            az += __shfl_xor_sync(0xffffffffu, az, 8);
            aw += __shfl_xor_sync(0xffffffffu, aw, 8);
            ax += __shfl_xor_sync(0xffffffffu, ax, 16);
            ay += __shfl_xor_sync(0xffffffffu, ay, 16);
            az += __shfl_xor_sync(0xffffffffu, az, 16);
            aw += __shfl_xor_sync(0xffffffffu, aw, 16);

            if (lane < 8) sred[warp][lane] = make_float4(ax, ay, az, aw);
            __syncthreads();
            if (threadIdx.x < 8) {
                float4 acc = sred[0][threadIdx.x];
#pragma unroll
                for (int k = 1; k < 16; k++) {
                    float4 tv = sred[k][threadIdx.x];
                    acc.x += tv.x; acc.y += tv.y; acc.z += tv.z; acc.w += tv.w;
                }
                float bs = sbias[rl];
                float4 o;
                o.x = fmaxf(acc.x + bs, 0.f);
                o.y = fmaxf(acc.y + bs, 0.f);
                o.z = fmaxf(acc.z + bs, 0.f);
                o.w = fmaxf(acc.w + bs, 0.f);
                *reinterpret_cast<float4*>(hout + ((r0 + rl) << 5) + (threadIdx.x << 2)) = o;
            }
            __syncthreads();
        }

        // ---- grid barrier (skip after last step) ----
        if (t < TSTEPS - 1) {
            __threadfence();              // publish writes (gpu scope)
            __syncthreads();
            if (threadIdx.x == 0) {
                int gen = g_gen;          // volatile: strong read, pre-arrival
                if (atomicAdd(&g_arrive, 1) == NB - 1) {
                    g_arrive = 0;
                    __threadfence();
                    g_gen = gen + 1;
                } else {
                    while (g_gen == gen) __nanosleep(32);
                }
            }
            __syncthreads();
            __threadfence();              // invalidate L1D before reading peers' h
        }
    }
}

// ---------------- fc1 partial: t1[b][m] += sum_n h[n][b] * w1[n][m] ----------------
__global__ void __launch_bounds__(256) k_fc1(const float* __restrict__ w1) {
    int t = threadIdx.x;
    int b  = t >> 3;            // 0..31
    int mg = (t & 7) << 3;      // m base: 0,8,...,56
    float acc[8];
#pragma unroll
    for (int j = 0; j < 8; j++) acc[j] = 0.f;

    int per = (NROWS + gridDim.x - 1) / gridDim.x;
    int n0 = blockIdx.x * per;
    int n1 = n0 + per; if (n1 > NROWS) n1 = NROWS;

    for (int n = n0; n < n1; n++) {
        float hv = g_h[0][(n << 5) | b];   // after 100 steps result is in parity 0
        const float4* w4 = reinterpret_cast<const float4*>(w1 + n * 64 + mg);
        float4 wa = __ldg(&w4[0]);
        float4 wb = __ldg(&w4[1]);
        acc[0] = fmaf(hv, wa.x, acc[0]);
        acc[1] = fmaf(hv, wa.y, acc[1]);
        acc[2] = fmaf(hv, wa.z, acc[2]);
        acc[3] = fmaf(hv, wa.w, acc[3]);
        acc[4] = fmaf(hv, wb.x, acc[4]);
        acc[5] = fmaf(hv, wb.y, acc[5]);
        acc[6] = fmaf(hv, wb.z, acc[6]);
        acc[7] = fmaf(hv, wb.w, acc[7]);
    }
#pragma unroll
    for (int j = 0; j < 8; j++) atomicAdd(&g_t1[b * 64 + mg + j], acc[j]);
}

// ---------------- fc2 ----------------
__global__ void k_fc2(const float* __restrict__ b1, const float* __restrict__ w2,
                      const float* __restrict__ b2, float* __restrict__ out) {
    int t = threadIdx.x;
    if (t >= BATCH * 10) return;
    int b = t / 10, j = t % 10;
    float acc = b2[j];
#pragma unroll 8
    for (int m = 0; m < 64; m++) {
        float u = fmaxf(g_t1[b * 64 + m] + b1[m], 0.f);
        acc = fmaf(u, w2[m * 10 + j], acc);
    }
    out[b * 10 + j] = acc;
}

// ---------------- launch ----------------
extern "C" void kernel_launch(void* const* d_in, const int* in_sizes, int n_in,
                              void* d_out, int out_size) {
    const float* x    = (const float*)d_in[0];
    const float* vals = (const float*)d_in[1];
    const float* bias = (const float*)d_in[2];
    const float* w1   = (const float*)d_in[3];
    const float* b1   = (const float*)d_in[4];
    const float* w2   = (const float*)d_in[5];
    const float* b2   = (const float*)d_in[6];
    const int*   rows = (const int*)d_in[7];
    const int*   cols = (const int*)d_in[8];
    (void)in_sizes; (void)n_in; (void)out_size;

    k_zero   <<<(NROWS + 255) / 256, 256>>>();
    k_hist   <<<(NNZ + 255) / 256, 256>>>(rows);
    k_scan   <<<1, 1024>>>();
    k_scatter<<<(NNZ + 255) / 256, 256>>>(rows, cols, vals);

    k_init_h <<<(NROWS * BATCH + 255) / 256, 256>>>(x);

    k_run<<<NB, 512>>>(bias);     // all 100 steps, persistent, grid barrier

    k_fc1<<<128, 256>>>(w1);
    k_fc2<<<1, 320>>>(b1, w2, b2, (float*)d_out);
}